// round 4
// baseline (speedup 1.0000x reference)
#include <cuda_runtime.h>
#include <cstdint>

// DownscaleLabel: label [8,1024,1024] int32 in {-1,0..6} -> out [8,1,64,64] f32.
// Per 16x16 tile: 8-class histogram (ignore -1 -> class 7 via &7), first-max
// argmax, -1 if argmax==7 or max_count < 192 (== ratio < 0.75, exact).
//
// Layout: 1 warp = 4 horizontally-adjacent tiles, 8 lanes per tile.
//   sub = lane&7: quad = sub&3 (which 16B of the 64B tile row),
//   rows = (sub>>2)*8 .. +7  (sub<4 -> rows 0-7, sub>=4 -> rows 8-15).
// Each thread: 8 int4 loads (32 px), ALL prefetched -> MLP=8.
// Histogram: 64-bit acc, 8x8-bit fields (max 32/thread).
// Reduce over 8 sub-lanes: xor1 (max 64), xor2 (max 128, still 8-bit), widen
// to 16-bit even/odd fields, xor4 (max 256). Lanes sub==0 emit 4 tiles.

static constexpr int SCALE = 16;
static constexpr int TILES_PER_IMG = 64 * 64;   // 4096
static constexpr int WARPS_PER_IMG = TILES_PER_IMG / 4;  // 1024

__global__ void downscale_label_kernel(const int* __restrict__ label,
                                       float* __restrict__ out,
                                       int n_warps) {
    const int wg   = (blockIdx.x * blockDim.x + threadIdx.x) >> 5;
    const int lane = threadIdx.x & 31;
    if (wg >= n_warps) return;

    const int b   = wg >> 10;                   // / WARPS_PER_IMG
    const int wi  = wg & (WARPS_PER_IMG - 1);
    const int th  = wi >> 4;                    // tile row (64), 16 warps/row
    const int twg = wi & 15;                    // group of 4 tiles

    const int tile = lane >> 3;                 // 0..3 within group
    const int sub  = lane & 7;
    const int quad = sub & 3;                   // int4 within 64B tile row
    const int row0 = (sub >> 2) * 8;            // 0 or 8

    // int4 index: image row = 256 int4. Tile col px = (twg*4+tile)*16.
    const int4* p = reinterpret_cast<const int4*>(label)
                    + ((size_t)b << 18)                     // b * 1M px / 4
                    + ((size_t)(th * 16 + row0) << 8)       // row * 256
                    + ((twg << 4) + (tile << 2) + quad);
    const int row_i4 = 256;

    // Prefetch all 8 loads (MLP = 8).
    int4 v[8];
#pragma unroll
    for (int r = 0; r < 8; ++r) v[r] = __ldg(p + r * row_i4);

    // Two interleaved 8x8-bit packed accumulators.
    unsigned long long a0 = 0ull, a1 = 0ull;
#pragma unroll
    for (int r = 0; r < 8; ++r) {
        a0 += 1ull << ((((unsigned)v[r].x & 7u) << 3));
        a1 += 1ull << ((((unsigned)v[r].y & 7u) << 3));
        a0 += 1ull << ((((unsigned)v[r].z & 7u) << 3));
        a1 += 1ull << ((((unsigned)v[r].w & 7u) << 3));
    }
    unsigned long long acc = a0 + a1;           // max 32 per 8-bit field

    // Reduce over the 8 sub-lanes of each tile.
    acc += __shfl_xor_sync(0xffffffffu, acc, 1);   // max 64
    acc += __shfl_xor_sync(0xffffffffu, acc, 2);   // max 128 (fits 8-bit)
    // Widen: even classes and odd classes into 16-bit fields.
    unsigned long long e = acc & 0x00FF00FF00FF00FFull;
    unsigned long long o = (acc >> 8) & 0x00FF00FF00FF00FFull;
    e += __shfl_xor_sync(0xffffffffu, e, 4);       // max 256
    o += __shfl_xor_sync(0xffffffffu, o, 4);

    if (sub == 0) {
        int counts[8];
#pragma unroll
        for (int i = 0; i < 4; ++i) {
            counts[2 * i]     = (int)((e >> (16 * i)) & 0xffffull);
            counts[2 * i + 1] = (int)((o >> (16 * i)) & 0xffffull);
        }
        int best = counts[0], arg = 0;
#pragma unroll
        for (int i = 1; i < 8; ++i) {
            if (counts[i] > best) { best = counts[i]; arg = i; }  // first-max
        }
        // ratio < 0.75  <=>  count < 192 (0.75 * 256 == 192 exactly)
        const int res = (arg == 7 || best < 192) ? -1 : arg;

        const int tw = (twg << 2) + tile;
        out[b * TILES_PER_IMG + th * 64 + tw] = (float)res;
    }
}

extern "C" void kernel_launch(void* const* d_in, const int* in_sizes, int n_in,
                              void* d_out, int out_size) {
    const int* label = (const int*)d_in[0];
    float* out = (float*)d_out;

    // 8M px / 256 px per tile / 4 tiles per warp = 8192 warps.
    const int n_tiles = in_sizes[0] / (SCALE * SCALE);
    const int n_warps = n_tiles / 4;

    const int threads = 256;                  // 8 warps/block -> 1024 blocks
    const int blocks = (n_warps * 32 + threads - 1) / threads;

    downscale_label_kernel<<<blocks, threads>>>(label, out, n_warps);
}

// round 6
// speedup vs baseline: 1.0257x; 1.0257x over previous
#include <cuda_runtime.h>
#include <cstdint>

// DownscaleLabel: label [8,1024,1024] int32 in {-1,0..6} -> out [8,1,64,64] f32.
// Per 16x16 tile: 8-class histogram (ignore -1 -> class 7 via &7), first-max
// argmax, -1 if argmax==7 or max_count < 192 (== ratio < 0.75, exact).
//
// Layout: 1 warp = 2 horizontally-adjacent tiles, 16 lanes per tile.
//   sub = lane&15: quad = sub&3 (which int4 of the 64B tile row),
//   rowgroup = sub>>2 (0..3) -> rows rowgroup*4 .. +3.
// Each thread: 4 int4 loads (16 px), all live at once -> true MLP=4 in 32 regs.
// Histogram: 64-bit acc, 8x8-bit fields (max 16/thread).
// Reduce over 16 sub-lanes: xor1,2,4 in 8-bit fields (max 128), widen to
// 16-bit even/odd fields, xor8 (max 256). Lanes sub==0 emit 2 tiles.

static constexpr int SCALE = 16;
static constexpr int TILES_PER_IMG = 64 * 64;            // 4096
static constexpr int WARPS_PER_IMG = TILES_PER_IMG / 2;  // 2048

__global__ void __launch_bounds__(256)
downscale_label_kernel(const int* __restrict__ label,
                       float* __restrict__ out,
                       int n_warps) {
    const int wg   = (blockIdx.x * blockDim.x + threadIdx.x) >> 5;
    const int lane = threadIdx.x & 31;
    if (wg >= n_warps) return;

    const int b   = wg >> 11;                   // / WARPS_PER_IMG (2048)
    const int wi  = wg & (WARPS_PER_IMG - 1);
    const int th  = wi >> 5;                    // tile row (64), 32 warps/row
    const int twg = wi & 31;                    // group of 2 tiles

    const int tile = lane >> 4;                 // 0..1
    const int sub  = lane & 15;
    const int quad = sub & 3;                   // int4 within 64B tile row
    const int rg   = sub >> 2;                  // row group 0..3 (4 rows each)

    // int4 index: image row = 256 int4. Tile col px = (twg*2+tile)*16.
    const int4* p = reinterpret_cast<const int4*>(label)
                    + ((size_t)b << 18)                      // b * 1M px / 4
                    + ((size_t)(th * 16 + rg * 4) << 8)      // row * 256
                    + ((twg << 3) + (tile << 2) + quad);

    // Front-batched loads: 4 int4 = 16 data regs, true MLP = 4.
    const int4 v0 = __ldg(p);
    const int4 v1 = __ldg(p + 256);
    const int4 v2 = __ldg(p + 512);
    const int4 v3 = __ldg(p + 768);

    // Two interleaved 8x8-bit packed accumulators (max 8 each -> sum max 16).
    unsigned long long a0 = 0ull, a1 = 0ull;
    a0 += 1ull << (((unsigned)v0.x & 7u) << 3);
    a1 += 1ull << (((unsigned)v0.y & 7u) << 3);
    a0 += 1ull << (((unsigned)v0.z & 7u) << 3);
    a1 += 1ull << (((unsigned)v0.w & 7u) << 3);
    a0 += 1ull << (((unsigned)v1.x & 7u) << 3);
    a1 += 1ull << (((unsigned)v1.y & 7u) << 3);
    a0 += 1ull << (((unsigned)v1.z & 7u) << 3);
    a1 += 1ull << (((unsigned)v1.w & 7u) << 3);
    a0 += 1ull << (((unsigned)v2.x & 7u) << 3);
    a1 += 1ull << (((unsigned)v2.y & 7u) << 3);
    a0 += 1ull << (((unsigned)v2.z & 7u) << 3);
    a1 += 1ull << (((unsigned)v2.w & 7u) << 3);
    a0 += 1ull << (((unsigned)v3.x & 7u) << 3);
    a1 += 1ull << (((unsigned)v3.y & 7u) << 3);
    a0 += 1ull << (((unsigned)v3.z & 7u) << 3);
    a1 += 1ull << (((unsigned)v3.w & 7u) << 3);
    unsigned long long acc = a0 + a1;           // max 16 per 8-bit field

    // Reduce over the 16 sub-lanes of each tile (8-bit safe up to 128).
    acc += __shfl_xor_sync(0xffffffffu, acc, 1);   // max 32
    acc += __shfl_xor_sync(0xffffffffu, acc, 2);   // max 64
    acc += __shfl_xor_sync(0xffffffffu, acc, 4);   // max 128
    // Widen: even / odd classes into 16-bit fields, final round.
    unsigned long long e = acc & 0x00FF00FF00FF00FFull;
    unsigned long long o = (acc >> 8) & 0x00FF00FF00FF00FFull;
    e += __shfl_xor_sync(0xffffffffu, e, 8);       // max 256
    o += __shfl_xor_sync(0xffffffffu, o, 8);

    if (sub == 0) {
        int counts[8];
#pragma unroll
        for (int i = 0; i < 4; ++i) {
            counts[2 * i]     = (int)((e >> (16 * i)) & 0xffffull);
            counts[2 * i + 1] = (int)((o >> (16 * i)) & 0xffffull);
        }
        int best = counts[0], arg = 0;
#pragma unroll
        for (int i = 1; i < 8; ++i) {
            if (counts[i] > best) { best = counts[i]; arg = i; }  // first-max
        }
        // ratio < 0.75  <=>  count < 192 (0.75 * 256 == 192 exactly)
        const int res = (arg == 7 || best < 192) ? -1 : arg;

        const int tw = (twg << 1) + tile;
        out[b * TILES_PER_IMG + th * 64 + tw] = (float)res;
    }
}

extern "C" void kernel_launch(void* const* d_in, const int* in_sizes, int n_in,
                              void* d_out, int out_size) {
    const int* label = (const int*)d_in[0];
    float* out = (float*)d_out;

    // 8M px / 256 px per tile / 2 tiles per warp = 16384 warps.
    const int n_tiles = in_sizes[0] / (SCALE * SCALE);
    const int n_warps = n_tiles / 2;

    const int threads = 256;                 // 8 warps/block -> 2048 blocks
    const int blocks = (n_warps * 32 + threads - 1) / threads;

    downscale_label_kernel<<<blocks, threads>>>(label, out, n_warps);
}